// round 1
// baseline (speedup 1.0000x reference)
#include <cuda_runtime.h>
#include <math.h>

#define N_NODES 50000
#define N_EDGES 1600000
#define DIM 128
#define NEG_SLOPE 0.01f

// ---------------- scratch (static device globals; no allocation) ----------------
__device__ float g_Wp[DIM * DIM];                    // sigmoid(mask) folded into W
__device__ float g_h[(size_t)N_NODES * DIM];         // projected features
__device__ float g_ssrc[N_NODES];
__device__ float g_sdst[N_NODES];
__device__ int   g_deg[N_NODES];
__device__ int   g_off[N_NODES + 1];
__device__ int   g_cur[N_NODES];
__device__ int   g_csr_src[N_EDGES];
__device__ float g_csr_sc[N_EDGES];

// ---------------- K0: fold sigmoid(mask) into W; zero degree histogram ----------
__global__ void prep_kernel(const float* __restrict__ W, const float* __restrict__ mask) {
    int i = blockIdx.x * blockDim.x + threadIdx.x;
    if (i < DIM * DIM) {
        int k = i >> 7;   // row of W (input dim)
        float s = 1.f / (1.f + __expf(-mask[k]));
        g_Wp[i] = W[i] * s;
    }
    if (i < N_NODES) g_deg[i] = 0;
}

// ---------------- K1: h = feat @ Wp + b  (64-row tiles, 96KB dynamic smem) ------
#define GEMM_TM 64
__global__ void gemm_kernel(const float* __restrict__ feat, const float* __restrict__ bias, int N) {
    extern __shared__ float sm[];
    float* sF = sm;                 // [64][128]
    float* sW = sm + GEMM_TM * DIM; // [128][128]
    int tid = threadIdx.x;
    int rb = blockIdx.x * GEMM_TM;

    // load Wp: 16384 floats = 4096 float4
    const float4* Wp4 = (const float4*)g_Wp;
    float4* sW4 = (float4*)sW;
#pragma unroll
    for (int i = 0; i < 16; i++) sW4[tid + i * 256] = Wp4[tid + i * 256];

    // load feat tile: 64x128 = 2048 float4
    float4* sF4 = (float4*)sF;
#pragma unroll
    for (int i = 0; i < 8; i++) {
        int idx = tid + i * 256;          // float4 index
        int r = idx >> 5;                 // 32 float4 per row
        float4 v = make_float4(0.f, 0.f, 0.f, 0.f);
        if (rb + r < N) v = ((const float4*)(feat + (size_t)(rb + r) * DIM))[idx & 31];
        sF4[idx] = v;
    }
    __syncthreads();

    int tx = tid & 15;        // 16 col groups
    int ty = tid >> 4;        // 16 row groups of 4 rows
    float acc[4][8];
#pragma unroll
    for (int i = 0; i < 4; i++)
#pragma unroll
        for (int j = 0; j < 8; j++) acc[i][j] = 0.f;

#pragma unroll 4
    for (int k = 0; k < 128; k++) {
        float a[4];
#pragma unroll
        for (int i = 0; i < 4; i++) a[i] = sF[(ty * 4 + i) * DIM + k];
        float4 b0 = *(const float4*)&sW[k * DIM + tx * 4];
        float4 b1 = *(const float4*)&sW[k * DIM + 64 + tx * 4];
#pragma unroll
        for (int i = 0; i < 4; i++) {
            acc[i][0] += a[i] * b0.x; acc[i][1] += a[i] * b0.y;
            acc[i][2] += a[i] * b0.z; acc[i][3] += a[i] * b0.w;
            acc[i][4] += a[i] * b1.x; acc[i][5] += a[i] * b1.y;
            acc[i][6] += a[i] * b1.z; acc[i][7] += a[i] * b1.w;
        }
    }

    float4 bb0 = *(const float4*)&bias[tx * 4];
    float4 bb1 = *(const float4*)&bias[64 + tx * 4];
#pragma unroll
    for (int i = 0; i < 4; i++) {
        int r = rb + ty * 4 + i;
        if (r < N) {
            float4 o0 = make_float4(acc[i][0] + bb0.x, acc[i][1] + bb0.y,
                                    acc[i][2] + bb0.z, acc[i][3] + bb0.w);
            float4 o1 = make_float4(acc[i][4] + bb1.x, acc[i][5] + bb1.y,
                                    acc[i][6] + bb1.z, acc[i][7] + bb1.w);
            float4* hp = (float4*)(g_h + (size_t)r * DIM);
            hp[tx] = o0;
            hp[16 + tx] = o1;
        }
    }
}

// ---------------- K2: per-node attention GEMVs (warp per node) ------------------
__global__ void score_kernel(const float* __restrict__ attn_w, int N) {
    int gw = (blockIdx.x * blockDim.x + threadIdx.x) >> 5;
    int lane = threadIdx.x & 31;
    if (gw >= N) return;
    float4 h4 = ((const float4*)(g_h + (size_t)gw * DIM))[lane];
    float4 a0 = ((const float4*)attn_w)[lane];        // attn_w[0:128]
    float4 a1 = ((const float4*)attn_w)[32 + lane];   // attn_w[128:256]
    float s1 = h4.x * a0.x + h4.y * a0.y + h4.z * a0.z + h4.w * a0.w;
    float s2 = h4.x * a1.x + h4.y * a1.y + h4.z * a1.z + h4.w * a1.w;
#pragma unroll
    for (int o = 16; o > 0; o >>= 1) {
        s1 += __shfl_xor_sync(0xffffffffu, s1, o);
        s2 += __shfl_xor_sync(0xffffffffu, s2, o);
    }
    if (lane == 0) { g_ssrc[gw] = s1; g_sdst[gw] = s2; }
}

// ---------------- K3: in-degree histogram --------------------------------------
__global__ void hist_kernel(const int* __restrict__ dst, int E) {
    for (int i = blockIdx.x * blockDim.x + threadIdx.x; i < E; i += gridDim.x * blockDim.x)
        atomicAdd(&g_deg[dst[i]], 1);
}

// ---------------- K4: single-block exclusive scan over degrees -----------------
__global__ void scan_kernel(int n) {
    __shared__ int wsum[32];
    __shared__ int carry;
    int tid = threadIdx.x, lane = tid & 31, w = tid >> 5;
    if (tid == 0) carry = 0;
    __syncthreads();
    for (int base = 0; base < n; base += 1024) {
        int i = base + tid;
        int v = (i < n) ? g_deg[i] : 0;
        int x = v;
#pragma unroll
        for (int o = 1; o < 32; o <<= 1) {
            int t = __shfl_up_sync(0xffffffffu, x, o);
            if (lane >= o) x += t;
        }
        if (lane == 31) wsum[w] = x;
        __syncthreads();
        if (w == 0) {
            int sv = wsum[lane];
            int y = sv;
#pragma unroll
            for (int o = 1; o < 32; o <<= 1) {
                int t = __shfl_up_sync(0xffffffffu, y, o);
                if (lane >= o) y += t;
            }
            wsum[lane] = y - sv;   // exclusive warp offsets
        }
        __syncthreads();
        int excl = carry + wsum[w] + (x - v);
        if (i < n) { g_off[i] = excl; g_cur[i] = excl; }
        __syncthreads();
        if (tid == 1023) carry += wsum[31] + x;  // block total
        __syncthreads();
    }
    if (tid == 0) g_off[n] = carry;
}

// ---------------- K5: edge score + CSR scatter ---------------------------------
__global__ void scatter_kernel(const int* __restrict__ src, const int* __restrict__ dst,
                               const float* __restrict__ attn_b, int E) {
    float ab = attn_b[0];
    for (int i = blockIdx.x * blockDim.x + threadIdx.x; i < E; i += gridDim.x * blockDim.x) {
        int u = src[i], v = dst[i];
        float sc = g_ssrc[u] + g_sdst[v] + ab;
        sc = (sc >= 0.f) ? sc : NEG_SLOPE * sc;   // leaky relu
        int p = atomicAdd(&g_cur[v], 1);
        g_csr_src[p] = u;
        g_csr_sc[p] = sc;
    }
}

// ---------------- K6: warp-per-dst segment softmax + weighted gather-sum -------
__global__ void agg_kernel(float* __restrict__ out, int N) {
    int gw = (blockIdx.x * blockDim.x + threadIdx.x) >> 5;
    if (gw >= N) return;
    int lane = threadIdx.x & 31;
    int s = g_off[gw], e = g_off[gw + 1];

    // pass 1: segment max
    float mx = -INFINITY;
    for (int i = s + lane; i < e; i += 32) mx = fmaxf(mx, g_csr_sc[i]);
#pragma unroll
    for (int o = 16; o > 0; o >>= 1) mx = fmaxf(mx, __shfl_xor_sync(0xffffffffu, mx, o));

    // pass 2: denom
    float den = 0.f;
    for (int i = s + lane; i < e; i += 32) den += __expf(g_csr_sc[i] - mx);
#pragma unroll
    for (int o = 16; o > 0; o >>= 1) den += __shfl_xor_sync(0xffffffffu, den, o);

    // pass 3: weighted accumulate — whole warp cooperates per edge (512B gather)
    float4 acc = make_float4(0.f, 0.f, 0.f, 0.f);
    for (int ib = s; ib < e; ib += 32) {
        int cnt = min(32, e - ib);
        int myu = 0; float myw = 0.f;
        if (lane < cnt) {
            myu = g_csr_src[ib + lane];
            myw = __expf(g_csr_sc[ib + lane] - mx);
        }
        for (int j = 0; j < cnt; j++) {
            int u = __shfl_sync(0xffffffffu, myu, j);
            float w = __shfl_sync(0xffffffffu, myw, j);
            float4 hv = ((const float4*)(g_h + (size_t)u * DIM))[lane];
            acc.x += w * hv.x; acc.y += w * hv.y;
            acc.z += w * hv.z; acc.w += w * hv.w;
        }
    }
    float inv = (den > 0.f) ? (1.f / den) : 0.f;
    float4 o4 = make_float4(acc.x * inv, acc.y * inv, acc.z * inv, acc.w * inv);
    ((float4*)(out + (size_t)gw * DIM))[lane] = o4;
}

// ---------------- launch --------------------------------------------------------
extern "C" void kernel_launch(void* const* d_in, const int* in_sizes, int n_in,
                              void* d_out, int out_size) {
    const float* feat   = (const float*)d_in[0];
    const int*   src    = (const int*)d_in[1];
    const int*   dst    = (const int*)d_in[2];
    const float* W      = (const float*)d_in[3];
    const float* bias   = (const float*)d_in[4];
    const float* attn_w = (const float*)d_in[5];
    const float* attn_b = (const float*)d_in[6];
    const float* mask   = (const float*)d_in[7];
    float* out = (float*)d_out;

    int N = in_sizes[0] / DIM;   // 50000
    int E = in_sizes[1];         // 1600000

    prep_kernel<<<(N_NODES + 255) / 256, 256>>>(W, mask);

    size_t smem = (size_t)(GEMM_TM * DIM + DIM * DIM) * sizeof(float);  // 96KB
    cudaFuncSetAttribute(gemm_kernel, cudaFuncAttributeMaxDynamicSharedMemorySize, (int)smem);
    gemm_kernel<<<(N + GEMM_TM - 1) / GEMM_TM, 256, smem>>>(feat, bias, N);

    score_kernel<<<(N * 32 + 255) / 256, 256>>>(attn_w, N);
    hist_kernel<<<1024, 256>>>(dst, E);
    scan_kernel<<<1, 1024>>>(N);
    scatter_kernel<<<1024, 256>>>(src, dst, attn_b, E);
    agg_kernel<<<(N * 32 + 255) / 256, 256>>>(out, N);
}

// round 3
// speedup vs baseline: 1.2283x; 1.2283x over previous
#include <cuda_runtime.h>
#include <math.h>

#define N_NODES 50000
#define N_EDGES 1600000
#define DIM 128
#define NEG_SLOPE 0.01f

// ---------------- scratch (static device globals; no allocation) ----------------
__device__ float g_Wp[DIM * DIM];                    // sigmoid(mask) folded into W
__device__ float g_h[(size_t)N_NODES * DIM];         // projected features
__device__ float g_ssrc[N_NODES];
__device__ float g_sdst[N_NODES];
__device__ int   g_deg[N_NODES];
__device__ int   g_off[N_NODES + 1];
__device__ int   g_cur[N_NODES];
__device__ int2  g_csr[N_EDGES];                     // packed {src, score-bits}
__device__ int   g_bsum[64];
__device__ int   g_bpre[64];

// ---------------- f32x2 packed FMA helpers (sm_103a) ----------------------------
__device__ __forceinline__ unsigned long long pack2(float lo, float hi) {
    unsigned long long r;
    asm("mov.b64 %0,{%1,%2};" : "=l"(r) : "f"(lo), "f"(hi));
    return r;
}
__device__ __forceinline__ void unpack2(unsigned long long v, float& lo, float& hi) {
    asm("mov.b64 {%0,%1},%2;" : "=f"(lo), "=f"(hi) : "l"(v));
}
__device__ __forceinline__ void fma2(unsigned long long& d, unsigned long long a, unsigned long long b) {
    asm("fma.rn.f32x2 %0,%1,%2,%0;" : "+l"(d) : "l"(a), "l"(b));
}

// ---------------- K0: fold sigmoid(mask) into W; zero degree histogram ----------
__global__ void prep_kernel(const float* __restrict__ W, const float* __restrict__ mask) {
    int i = blockIdx.x * blockDim.x + threadIdx.x;
    if (i < DIM * DIM) {
        int k = i >> 7;
        float s = 1.f / (1.f + __expf(-mask[k]));
        g_Wp[i] = W[i] * s;
    }
    if (i < N_NODES) g_deg[i] = 0;
}

// ---------------- K1: h = feat @ Wp + b  (64-row tile, 8x8 microtile, f32x2) ----
#define GB_M 64
__global__ __launch_bounds__(128) void gemm_kernel(const float* __restrict__ feat,
                                                   const float* __restrict__ bias, int N) {
    extern __shared__ float sm[];
    float* sFT = sm;              // [128 k][64 m] transposed feat tile (32KB)
    float* sW  = sm + 128 * 64;   // [128 k][128 n] (64KB)
    int tid = threadIdx.x;
    int rb = blockIdx.x * GB_M;

    // load W: 4096 float4, 128 threads -> 32 iters, coalesced
    const float4* Wp4 = (const float4*)g_Wp;
    float4* sW4 = (float4*)sW;
#pragma unroll
    for (int i = 0; i < 32; i++) sW4[tid + i * 128] = Wp4[tid + i * 128];

    // load feat tile transposed: 1024 units of 8 floats along k
#pragma unroll
    for (int it = 0; it < 8; it++) {
        int idx = tid + it * 128;
        int m = idx & 63, kq = idx >> 6;      // kq 0..15
        int row = rb + m;
        float4 v0 = make_float4(0.f, 0.f, 0.f, 0.f), v1 = v0;
        if (row < N) {
            const float4* fp = (const float4*)(feat + (size_t)row * DIM);
            v0 = fp[kq * 2]; v1 = fp[kq * 2 + 1];
        }
        int kb = kq * 8;
        sFT[(kb + 0) * 64 + m] = v0.x; sFT[(kb + 1) * 64 + m] = v0.y;
        sFT[(kb + 2) * 64 + m] = v0.z; sFT[(kb + 3) * 64 + m] = v0.w;
        sFT[(kb + 4) * 64 + m] = v1.x; sFT[(kb + 5) * 64 + m] = v1.y;
        sFT[(kb + 6) * 64 + m] = v1.z; sFT[(kb + 7) * 64 + m] = v1.w;
    }
    __syncthreads();

    int tx = tid & 15;   // col group of 8
    int ty = tid >> 4;   // row group of 8 (0..7)

    unsigned long long acc[8][4];
#pragma unroll
    for (int i = 0; i < 8; i++)
#pragma unroll
        for (int j = 0; j < 4; j++) acc[i][j] = 0ULL;

#pragma unroll 4
    for (int k = 0; k < 128; k++) {
        const float4* ap = (const float4*)&sFT[k * 64 + ty * 8];
        float4 a0 = ap[0], a1 = ap[1];
        const ulonglong2* bp2 = (const ulonglong2*)&sW[k * 128 + tx * 8];
        ulonglong2 bq0 = bp2[0], bq1 = bp2[1];
        unsigned long long bp[4] = {bq0.x, bq0.y, bq1.x, bq1.y};
        unsigned long long ad[8];
        ad[0] = pack2(a0.x, a0.x); ad[1] = pack2(a0.y, a0.y);
        ad[2] = pack2(a0.z, a0.z); ad[3] = pack2(a0.w, a0.w);
        ad[4] = pack2(a1.x, a1.x); ad[5] = pack2(a1.y, a1.y);
        ad[6] = pack2(a1.z, a1.z); ad[7] = pack2(a1.w, a1.w);
#pragma unroll
        for (int i = 0; i < 8; i++)
#pragma unroll
            for (int j = 0; j < 4; j++) fma2(acc[i][j], ad[i], bp[j]);
    }

    float4 bb0 = *(const float4*)&bias[tx * 8];
    float4 bb1 = *(const float4*)&bias[tx * 8 + 4];
#pragma unroll
    for (int i = 0; i < 8; i++) {
        int row = rb + ty * 8 + i;
        if (row < N) {
            float o[8];
            unpack2(acc[i][0], o[0], o[1]);
            unpack2(acc[i][1], o[2], o[3]);
            unpack2(acc[i][2], o[4], o[5]);
            unpack2(acc[i][3], o[6], o[7]);
            float4 w0 = make_float4(o[0] + bb0.x, o[1] + bb0.y, o[2] + bb0.z, o[3] + bb0.w);
            float4 w1 = make_float4(o[4] + bb1.x, o[5] + bb1.y, o[6] + bb1.z, o[7] + bb1.w);
            float4* hp = (float4*)(g_h + (size_t)row * DIM);
            hp[tx * 2] = w0;
            hp[tx * 2 + 1] = w1;
        }
    }
}

// ---------------- K2: per-node attention GEMVs (warp per node) ------------------
__global__ void score_kernel(const float* __restrict__ attn_w, int N) {
    int gw = (blockIdx.x * blockDim.x + threadIdx.x) >> 5;
    int lane = threadIdx.x & 31;
    if (gw >= N) return;
    float4 h4 = ((const float4*)(g_h + (size_t)gw * DIM))[lane];
    float4 a0 = ((const float4*)attn_w)[lane];
    float4 a1 = ((const float4*)attn_w)[32 + lane];
    float s1 = h4.x * a0.x + h4.y * a0.y + h4.z * a0.z + h4.w * a0.w;
    float s2 = h4.x * a1.x + h4.y * a1.y + h4.z * a1.z + h4.w * a1.w;
#pragma unroll
    for (int o = 16; o > 0; o >>= 1) {
        s1 += __shfl_xor_sync(0xffffffffu, s1, o);
        s2 += __shfl_xor_sync(0xffffffffu, s2, o);
    }
    if (lane == 0) { g_ssrc[gw] = s1; g_sdst[gw] = s2; }
}

// ---------------- K3: in-degree histogram (vectorized) --------------------------
__global__ void hist_kernel(const int* __restrict__ dst, int E) {
    int i = blockIdx.x * blockDim.x + threadIdx.x;
    int i4 = i * 4;
    if (i4 + 3 < E) {
        int4 v = ((const int4*)dst)[i];
        atomicAdd(&g_deg[v.x], 1);
        atomicAdd(&g_deg[v.y], 1);
        atomicAdd(&g_deg[v.z], 1);
        atomicAdd(&g_deg[v.w], 1);
    } else {
        for (int j = i4; j < E; j++) atomicAdd(&g_deg[dst[j]], 1);
    }
}

// ---------------- K4: hierarchical exclusive scan -------------------------------
#define SCAN_CH 2048
__global__ void scan1_kernel(int n) {
    __shared__ int wsum[16];
    int b = blockIdx.x, tid = threadIdx.x;
    int base = b * SCAN_CH + tid * 4;
    int v0 = (base + 0 < n) ? g_deg[base + 0] : 0;
    int v1 = (base + 1 < n) ? g_deg[base + 1] : 0;
    int v2 = (base + 2 < n) ? g_deg[base + 2] : 0;
    int v3 = (base + 3 < n) ? g_deg[base + 3] : 0;
    int t = v0 + v1 + v2 + v3;
    int x = t;
    int lane = tid & 31, w = tid >> 5;
#pragma unroll
    for (int o = 1; o < 32; o <<= 1) {
        int tt = __shfl_up_sync(0xffffffffu, x, o);
        if (lane >= o) x += tt;
    }
    if (lane == 31) wsum[w] = x;
    __syncthreads();
    if (tid < 16) {
        int sv = wsum[tid];
        int y = sv;
#pragma unroll
        for (int o = 1; o < 16; o <<= 1) {
            int tt = __shfl_up_sync(0xffffu, y, o);
            if (tid >= o) y += tt;
        }
        wsum[tid] = y - sv;  // exclusive
    }
    __syncthreads();
    int excl = wsum[w] + (x - t);   // exclusive start within block
    if (base + 0 < n) g_off[base + 0] = excl;
    if (base + 1 < n) g_off[base + 1] = excl + v0;
    if (base + 2 < n) g_off[base + 2] = excl + v0 + v1;
    if (base + 3 < n) g_off[base + 3] = excl + v0 + v1 + v2;
    if (tid == blockDim.x - 1) g_bsum[b] = excl + t;  // block total
}

__global__ void scan2_kernel(int nb, int n) {
    int tid = threadIdx.x;
    int v = (tid < nb) ? g_bsum[tid] : 0;
    int x = v;
#pragma unroll
    for (int o = 1; o < 32; o <<= 1) {
        int tt = __shfl_up_sync(0xffffffffu, x, o);
        if (tid >= o) x += tt;
    }
    g_bpre[tid] = x - v;
    if (tid == 31) g_off[n] = x;  // grand total
}

__global__ void scan3_kernel(int n) {
    int i = blockIdx.x * blockDim.x + threadIdx.x;
    if (i < n) {
        int o = g_off[i] + g_bpre[i / SCAN_CH];
        g_off[i] = o;
        g_cur[i] = o;
    }
}

// ---------------- K5: edge score + CSR scatter (vectorized, packed records) -----
__global__ void scatter_kernel(const int* __restrict__ src, const int* __restrict__ dst,
                               const float* __restrict__ attn_b, int E) {
    float ab = attn_b[0];
    int i = blockIdx.x * blockDim.x + threadIdx.x;
    int i4 = i * 4;
    if (i4 >= E) return;
    if (i4 + 3 < E) {
        int4 u4 = ((const int4*)src)[i];
        int4 v4 = ((const int4*)dst)[i];
        int us[4] = {u4.x, u4.y, u4.z, u4.w};
        int vs[4] = {v4.x, v4.y, v4.z, v4.w};
#pragma unroll
        for (int j = 0; j < 4; j++) {
            float sc = g_ssrc[us[j]] + g_sdst[vs[j]] + ab;
            sc = (sc >= 0.f) ? sc : NEG_SLOPE * sc;
            int p = atomicAdd(&g_cur[vs[j]], 1);
            g_csr[p] = make_int2(us[j], __float_as_int(sc));
        }
    } else {
        for (int j = i4; j < E; j++) {
            int u = src[j], v = dst[j];
            float sc = g_ssrc[u] + g_sdst[v] + ab;
            sc = (sc >= 0.f) ? sc : NEG_SLOPE * sc;
            int p = atomicAdd(&g_cur[v], 1);
            g_csr[p] = make_int2(u, __float_as_int(sc));
        }
    }
}

// ---------------- K6: warp-per-dst segment softmax + weighted gather-sum --------
__global__ void agg_kernel(float* __restrict__ out, int N) {
    int gw = (blockIdx.x * blockDim.x + threadIdx.x) >> 5;
    if (gw >= N) return;
    int lane = threadIdx.x & 31;
    int s = g_off[gw], e = g_off[gw + 1];

    // pass 1: segment max
    float mx = -INFINITY;
    for (int i = s + lane; i < e; i += 32) mx = fmaxf(mx, __int_as_float(g_csr[i].y));
#pragma unroll
    for (int o = 16; o > 0; o >>= 1) mx = fmaxf(mx, __shfl_xor_sync(0xffffffffu, mx, o));

    // pass 2: fused denom + weighted accumulate (MLP=4 via 4 acc chains)
    float4 acc0 = make_float4(0.f, 0.f, 0.f, 0.f);
    float4 acc1 = acc0, acc2 = acc0, acc3 = acc0;
    float den = 0.f;
    for (int ib = s; ib < e; ib += 32) {
        int cnt = min(32, e - ib);
        int myu = 0; float myw = 0.f;
        if (lane < cnt) {
            int2 p = g_csr[ib + lane];
            myu = p.x;
            myw = __expf(__int_as_float(p.y) - mx);
        }
        den += myw;
        int j = 0;
        for (; j + 4 <= cnt; j += 4) {
            int u0 = __shfl_sync(0xffffffffu, myu, j);
            int u1 = __shfl_sync(0xffffffffu, myu, j + 1);
            int u2 = __shfl_sync(0xffffffffu, myu, j + 2);
            int u3 = __shfl_sync(0xffffffffu, myu, j + 3);
            float w0 = __shfl_sync(0xffffffffu, myw, j);
            float w1 = __shfl_sync(0xffffffffu, myw, j + 1);
            float w2 = __shfl_sync(0xffffffffu, myw, j + 2);
            float w3 = __shfl_sync(0xffffffffu, myw, j + 3);
            float4 h0 = ((const float4*)(g_h + (size_t)u0 * DIM))[lane];
            float4 h1 = ((const float4*)(g_h + (size_t)u1 * DIM))[lane];
            float4 h2 = ((const float4*)(g_h + (size_t)u2 * DIM))[lane];
            float4 h3 = ((const float4*)(g_h + (size_t)u3 * DIM))[lane];
            acc0.x += w0 * h0.x; acc0.y += w0 * h0.y; acc0.z += w0 * h0.z; acc0.w += w0 * h0.w;
            acc1.x += w1 * h1.x; acc1.y += w1 * h1.y; acc1.z += w1 * h1.z; acc1.w += w1 * h1.w;
            acc2.x += w2 * h2.x; acc2.y += w2 * h2.y; acc2.z += w2 * h2.z; acc2.w += w2 * h2.w;
            acc3.x += w3 * h3.x; acc3.y += w3 * h3.y; acc3.z += w3 * h3.z; acc3.w += w3 * h3.w;
        }
        for (; j < cnt; j++) {
            int u = __shfl_sync(0xffffffffu, myu, j);
            float w = __shfl_sync(0xffffffffu, myw, j);
            float4 hv = ((const float4*)(g_h + (size_t)u * DIM))[lane];
            acc0.x += w * hv.x; acc0.y += w * hv.y; acc0.z += w * hv.z; acc0.w += w * hv.w;
        }
    }
#pragma unroll
    for (int o = 16; o > 0; o >>= 1) den += __shfl_xor_sync(0xffffffffu, den, o);

    float inv = (den > 0.f) ? (1.f / den) : 0.f;
    float4 o4 = make_float4((acc0.x + acc1.x + acc2.x + acc3.x) * inv,
                            (acc0.y + acc1.y + acc2.y + acc3.y) * inv,
                            (acc0.z + acc1.z + acc2.z + acc3.z) * inv,
                            (acc0.w + acc1.w + acc2.w + acc3.w) * inv);
    ((float4*)(out + (size_t)gw * DIM))[lane] = o4;
}

// ---------------- launch --------------------------------------------------------
extern "C" void kernel_launch(void* const* d_in, const int* in_sizes, int n_in,
                              void* d_out, int out_size) {
    const float* feat   = (const float*)d_in[0];
    const int*   src    = (const int*)d_in[1];
    const int*   dst    = (const int*)d_in[2];
    const float* W      = (const float*)d_in[3];
    const float* bias   = (const float*)d_in[4];
    const float* attn_w = (const float*)d_in[5];
    const float* attn_b = (const float*)d_in[6];
    const float* mask   = (const float*)d_in[7];
    float* out = (float*)d_out;

    int N = in_sizes[0] / DIM;   // 50000
    int E = in_sizes[1];         // 1600000

    prep_kernel<<<(N_NODES + 255) / 256, 256>>>(W, mask);

    size_t smem = (size_t)(128 * 64 + 128 * 128) * sizeof(float);  // 96KB
    cudaFuncSetAttribute(gemm_kernel, cudaFuncAttributeMaxDynamicSharedMemorySize, (int)smem);
    gemm_kernel<<<(N + GB_M - 1) / GB_M, 128, smem>>>(feat, bias, N);

    score_kernel<<<(N * 32 + 255) / 256, 256>>>(attn_w, N);

    int e4 = (E + 3) / 4;
    hist_kernel<<<(e4 + 255) / 256, 256>>>(dst, E);

    int nb = (N + SCAN_CH - 1) / SCAN_CH;   // 25
    scan1_kernel<<<nb, 512>>>(N);
    scan2_kernel<<<1, 32>>>(nb, N);
    scan3_kernel<<<(N + 255) / 256, 256>>>(N);

    scatter_kernel<<<(e4 + 255) / 256, 256>>>(src, dst, attn_b, E);

    agg_kernel<<<(N * 32 + 255) / 256, 256>>>(out, N);
}

// round 4
// speedup vs baseline: 1.5505x; 1.2624x over previous
#include <cuda_runtime.h>
#include <cuda_fp16.h>
#include <math.h>

#define N_NODES 50000
#define N_EDGES 1600000
#define DIM 128
#define NEG_SLOPE 0.01f

// ---------------- scratch (static device globals; no allocation) ----------------
__device__ float  g_Wp[DIM * DIM];                   // sigmoid(mask) folded into W
__device__ __half g_hh[(size_t)N_NODES * DIM];       // projected features (fp16)
__device__ float  g_ssrc[N_NODES];
__device__ float  g_sdst[N_NODES];
__device__ int    g_deg[N_NODES];
__device__ int    g_off[N_NODES + 1];
__device__ int    g_cur[N_NODES];
__device__ int2   g_csr[N_EDGES];                    // packed {src, s_src-bits}
__device__ int    g_bsum[64];
__device__ int    g_bpre[64];

// ---------------- f32x2 packed FMA helpers (sm_103a) ----------------------------
__device__ __forceinline__ unsigned long long pack2(float lo, float hi) {
    unsigned long long r;
    asm("mov.b64 %0,{%1,%2};" : "=l"(r) : "f"(lo), "f"(hi));
    return r;
}
__device__ __forceinline__ void unpack2(unsigned long long v, float& lo, float& hi) {
    asm("mov.b64 {%0,%1},%2;" : "=f"(lo), "=f"(hi) : "l"(v));
}
__device__ __forceinline__ void fma2(unsigned long long& d, unsigned long long a, unsigned long long b) {
    asm("fma.rn.f32x2 %0,%1,%2,%0;" : "+l"(d) : "l"(a), "l"(b));
}

// ---------------- K0a: fold sigmoid(mask) into W --------------------------------
__global__ void prep_w_kernel(const float* __restrict__ W, const float* __restrict__ mask) {
    int i = blockIdx.x * blockDim.x + threadIdx.x;
    if (i < DIM * DIM) {
        int k = i >> 7;
        float s = 1.f / (1.f + __expf(-mask[k]));
        g_Wp[i] = W[i] * s;
    }
}

// ---------------- K0b: zero degree histogram ------------------------------------
__global__ void zero_deg_kernel(int n) {
    int i = blockIdx.x * blockDim.x + threadIdx.x;
    if (i < n) g_deg[i] = 0;
}

// ---------------- K1: h = feat @ Wp + b (fp16 out) + fused attention GEMVs ------
#define GB_M 64
__global__ __launch_bounds__(128) void gemm_kernel(const float* __restrict__ feat,
                                                   const float* __restrict__ bias,
                                                   const float* __restrict__ attn_w, int N) {
    extern __shared__ float sm[];
    float* sFT = sm;              // [128 k][64 m] transposed feat tile (32KB)
    float* sW  = sm + 128 * 64;   // [128 k][128 n] (64KB)
    int tid = threadIdx.x;
    int rb = blockIdx.x * GB_M;

    // load W: 4096 float4, coalesced
    const float4* Wp4 = (const float4*)g_Wp;
    float4* sW4 = (float4*)sW;
#pragma unroll
    for (int i = 0; i < 32; i++) sW4[tid + i * 128] = Wp4[tid + i * 128];

    // load feat tile transposed
#pragma unroll
    for (int it = 0; it < 8; it++) {
        int idx = tid + it * 128;
        int m = idx & 63, kq = idx >> 6;
        int row = rb + m;
        float4 v0 = make_float4(0.f, 0.f, 0.f, 0.f), v1 = v0;
        if (row < N) {
            const float4* fp = (const float4*)(feat + (size_t)row * DIM);
            v0 = fp[kq * 2]; v1 = fp[kq * 2 + 1];
        }
        int kb = kq * 8;
        sFT[(kb + 0) * 64 + m] = v0.x; sFT[(kb + 1) * 64 + m] = v0.y;
        sFT[(kb + 2) * 64 + m] = v0.z; sFT[(kb + 3) * 64 + m] = v0.w;
        sFT[(kb + 4) * 64 + m] = v1.x; sFT[(kb + 5) * 64 + m] = v1.y;
        sFT[(kb + 6) * 64 + m] = v1.z; sFT[(kb + 7) * 64 + m] = v1.w;
    }
    __syncthreads();

    int tx = tid & 15;   // col group of 8
    int ty = tid >> 4;   // row group of 8

    unsigned long long acc[8][4];
#pragma unroll
    for (int i = 0; i < 8; i++)
#pragma unroll
        for (int j = 0; j < 4; j++) acc[i][j] = 0ULL;

#pragma unroll 4
    for (int k = 0; k < 128; k++) {
        const float4* ap = (const float4*)&sFT[k * 64 + ty * 8];
        float4 a0 = ap[0], a1 = ap[1];
        const ulonglong2* bp2 = (const ulonglong2*)&sW[k * 128 + tx * 8];
        ulonglong2 bq0 = bp2[0], bq1 = bp2[1];
        unsigned long long bp[4] = {bq0.x, bq0.y, bq1.x, bq1.y};
        unsigned long long ad[8];
        ad[0] = pack2(a0.x, a0.x); ad[1] = pack2(a0.y, a0.y);
        ad[2] = pack2(a0.z, a0.z); ad[3] = pack2(a0.w, a0.w);
        ad[4] = pack2(a1.x, a1.x); ad[5] = pack2(a1.y, a1.y);
        ad[6] = pack2(a1.z, a1.z); ad[7] = pack2(a1.w, a1.w);
#pragma unroll
        for (int i = 0; i < 8; i++)
#pragma unroll
            for (int j = 0; j < 4; j++) fma2(acc[i][j], ad[i], bp[j]);
    }

    // epilogue: bias, fp16 store, fused attention partial dots
    float4 bb0 = *(const float4*)&bias[tx * 8];
    float4 bb1 = *(const float4*)&bias[tx * 8 + 4];
    float aw1[8], aw2[8];
    {
        const float4* aw4 = (const float4*)attn_w;
        float4 t0 = aw4[tx * 2], t1 = aw4[tx * 2 + 1];
        float4 t2 = aw4[32 + tx * 2], t3 = aw4[32 + tx * 2 + 1];
        aw1[0]=t0.x; aw1[1]=t0.y; aw1[2]=t0.z; aw1[3]=t0.w;
        aw1[4]=t1.x; aw1[5]=t1.y; aw1[6]=t1.z; aw1[7]=t1.w;
        aw2[0]=t2.x; aw2[1]=t2.y; aw2[2]=t2.z; aw2[3]=t2.w;
        aw2[4]=t3.x; aw2[5]=t3.y; aw2[6]=t3.z; aw2[7]=t3.w;
    }

#pragma unroll
    for (int i = 0; i < 8; i++) {
        int row = rb + ty * 8 + i;
        float o[8];
        unpack2(acc[i][0], o[0], o[1]);
        unpack2(acc[i][1], o[2], o[3]);
        unpack2(acc[i][2], o[4], o[5]);
        unpack2(acc[i][3], o[6], o[7]);
        o[0]+=bb0.x; o[1]+=bb0.y; o[2]+=bb0.z; o[3]+=bb0.w;
        o[4]+=bb1.x; o[5]+=bb1.y; o[6]+=bb1.z; o[7]+=bb1.w;

        // fp16 store (8 halves = 16B per thread)
        __half2 h0 = __floats2half2_rn(o[0], o[1]);
        __half2 h1 = __floats2half2_rn(o[2], o[3]);
        __half2 h2 = __floats2half2_rn(o[4], o[5]);
        __half2 h3 = __floats2half2_rn(o[6], o[7]);
        uint4 st;
        st.x = *reinterpret_cast<unsigned*>(&h0);
        st.y = *reinterpret_cast<unsigned*>(&h1);
        st.z = *reinterpret_cast<unsigned*>(&h2);
        st.w = *reinterpret_cast<unsigned*>(&h3);
        if (row < N)
            *reinterpret_cast<uint4*>(&g_hh[(size_t)row * DIM + tx * 8]) = st;

        // attention partial dots + 16-lane reduce
        float p1 = 0.f, p2 = 0.f;
#pragma unroll
        for (int c = 0; c < 8; c++) { p1 += o[c] * aw1[c]; p2 += o[c] * aw2[c]; }
#pragma unroll
        for (int off = 8; off >= 1; off >>= 1) {
            p1 += __shfl_xor_sync(0xffffffffu, p1, off);
            p2 += __shfl_xor_sync(0xffffffffu, p2, off);
        }
        if (tx == 0 && row < N) { g_ssrc[row] = p1; g_sdst[row] = p2; }
    }
}

// ---------------- K3: in-degree histogram (vectorized) --------------------------
__global__ void hist_kernel(const int* __restrict__ dst, int E) {
    int i = blockIdx.x * blockDim.x + threadIdx.x;
    int i4 = i * 4;
    if (i4 + 3 < E) {
        int4 v = ((const int4*)dst)[i];
        atomicAdd(&g_deg[v.x], 1);
        atomicAdd(&g_deg[v.y], 1);
        atomicAdd(&g_deg[v.z], 1);
        atomicAdd(&g_deg[v.w], 1);
    } else {
        for (int j = i4; j < E; j++) atomicAdd(&g_deg[dst[j]], 1);
    }
}

// ---------------- K4: hierarchical exclusive scan -------------------------------
#define SCAN_CH 2048
__global__ void scan1_kernel(int n) {
    __shared__ int wsum[16];
    int b = blockIdx.x, tid = threadIdx.x;
    int base = b * SCAN_CH + tid * 4;
    int v0 = (base + 0 < n) ? g_deg[base + 0] : 0;
    int v1 = (base + 1 < n) ? g_deg[base + 1] : 0;
    int v2 = (base + 2 < n) ? g_deg[base + 2] : 0;
    int v3 = (base + 3 < n) ? g_deg[base + 3] : 0;
    int t = v0 + v1 + v2 + v3;
    int x = t;
    int lane = tid & 31, w = tid >> 5;
#pragma unroll
    for (int o = 1; o < 32; o <<= 1) {
        int tt = __shfl_up_sync(0xffffffffu, x, o);
        if (lane >= o) x += tt;
    }
    if (lane == 31) wsum[w] = x;
    __syncthreads();
    if (tid < 16) {
        int sv = wsum[tid];
        int y = sv;
#pragma unroll
        for (int o = 1; o < 16; o <<= 1) {
            int tt = __shfl_up_sync(0xffffu, y, o);
            if (tid >= o) y += tt;
        }
        wsum[tid] = y - sv;
    }
    __syncthreads();
    int excl = wsum[w] + (x - t);
    if (base + 0 < n) g_off[base + 0] = excl;
    if (base + 1 < n) g_off[base + 1] = excl + v0;
    if (base + 2 < n) g_off[base + 2] = excl + v0 + v1;
    if (base + 3 < n) g_off[base + 3] = excl + v0 + v1 + v2;
    if (tid == blockDim.x - 1) g_bsum[b] = excl + t;
}

__global__ void scan2_kernel(int nb, int n) {
    int tid = threadIdx.x;
    int v = (tid < nb) ? g_bsum[tid] : 0;
    int x = v;
#pragma unroll
    for (int o = 1; o < 32; o <<= 1) {
        int tt = __shfl_up_sync(0xffffffffu, x, o);
        if (tid >= o) x += tt;
    }
    g_bpre[tid] = x - v;
    if (tid == 31) g_off[n] = x;
}

__global__ void scan3_kernel(int n) {
    int i = blockIdx.x * blockDim.x + threadIdx.x;
    if (i < n) {
        int o = g_off[i] + g_bpre[i / SCAN_CH];
        g_off[i] = o;
        g_cur[i] = o;
    }
}

// ---------------- K5: CSR scatter (src + raw s_src only; leaky/sdst in agg) -----
__global__ void scatter_kernel(const int* __restrict__ src, const int* __restrict__ dst, int E) {
    int i = blockIdx.x * blockDim.x + threadIdx.x;
    int i4 = i * 4;
    if (i4 >= E) return;
    if (i4 + 3 < E) {
        int4 u4 = ((const int4*)src)[i];
        int4 v4 = ((const int4*)dst)[i];
        int us[4] = {u4.x, u4.y, u4.z, u4.w};
        int vs[4] = {v4.x, v4.y, v4.z, v4.w};
#pragma unroll
        for (int j = 0; j < 4; j++) {
            float sc = g_ssrc[us[j]];
            int p = atomicAdd(&g_cur[vs[j]], 1);
            g_csr[p] = make_int2(us[j], __float_as_int(sc));
        }
    } else {
        for (int j = i4; j < E; j++) {
            int u = src[j], v = dst[j];
            float sc = g_ssrc[u];
            int p = atomicAdd(&g_cur[v], 1);
            g_csr[p] = make_int2(u, __float_as_int(sc));
        }
    }
}

// ---------------- K6: warp-per-dst softmax + fp16 gather (2 edges/warp-step) ----
__device__ __forceinline__ void acc8(float* acc, uint4 hv, float w) {
    __half2 h0 = *reinterpret_cast<__half2*>(&hv.x);
    __half2 h1 = *reinterpret_cast<__half2*>(&hv.y);
    __half2 h2 = *reinterpret_cast<__half2*>(&hv.z);
    __half2 h3 = *reinterpret_cast<__half2*>(&hv.w);
    float2 f0 = __half22float2(h0), f1 = __half22float2(h1);
    float2 f2 = __half22float2(h2), f3 = __half22float2(h3);
    acc[0] += w * f0.x; acc[1] += w * f0.y;
    acc[2] += w * f1.x; acc[3] += w * f1.y;
    acc[4] += w * f2.x; acc[5] += w * f2.y;
    acc[6] += w * f3.x; acc[7] += w * f3.y;
}

__global__ void agg_kernel(float* __restrict__ out, const float* __restrict__ attn_b, int N) {
    int gw = (blockIdx.x * blockDim.x + threadIdx.x) >> 5;
    if (gw >= N) return;
    int lane = threadIdx.x & 31;
    int grp = lane >> 4, sub = lane & 15;
    int s = g_off[gw], e = g_off[gw + 1];
    float sdv = g_sdst[gw] + attn_b[0];

    // pass 1: segment max over raw s_src (leaky is monotone -> commute)
    float mxr = -INFINITY;
    for (int i = s + lane; i < e; i += 32) mxr = fmaxf(mxr, __int_as_float(g_csr[i].y));
#pragma unroll
    for (int o = 16; o > 0; o >>= 1) mxr = fmaxf(mxr, __shfl_xor_sync(0xffffffffu, mxr, o));
    float tmx = mxr + sdv;
    float mxs = (tmx >= 0.f) ? tmx : NEG_SLOPE * tmx;

    // pass 2: denominator (csr is L1-hot from pass 1)
    float den = 0.f;
    for (int i = s + lane; i < e; i += 32) {
        float r = __int_as_float(g_csr[i].y) + sdv;
        r = (r >= 0.f) ? r : NEG_SLOPE * r;
        den += __expf(r - mxs);
    }
#pragma unroll
    for (int o = 16; o > 0; o >>= 1) den += __shfl_xor_sync(0xffffffffu, den, o);

    // pass 3: gather-accumulate, 2 edges per warp-step, 4 steps unrolled (MLP 4)
    float acc[8] = {0.f, 0.f, 0.f, 0.f, 0.f, 0.f, 0.f, 0.f};
    int jb = s;
    for (; jb + 8 <= e; jb += 8) {
#pragma unroll
        for (int tt = 0; tt < 4; tt++) {
            int2 p = g_csr[jb + 2 * tt + grp];
            float r = __int_as_float(p.y) + sdv;
            r = (r >= 0.f) ? r : NEG_SLOPE * r;
            float w = __expf(r - mxs);
            uint4 hv = *reinterpret_cast<const uint4*>(&g_hh[(size_t)p.x * DIM + sub * 8]);
            acc8(acc, hv, w);
        }
    }
    for (; jb < e; jb += 2) {
        int j = jb + grp;
        int2 p = (j < e) ? g_csr[j] : make_int2(0, (int)0xFF800000);
        float r = __int_as_float(p.y) + sdv;
        r = (r >= 0.f) ? r : NEG_SLOPE * r;
        float w = __expf(r - mxs);
        uint4 hv = *reinterpret_cast<const uint4*>(&g_hh[(size_t)p.x * DIM + sub * 8]);
        acc8(acc, hv, w);
    }

    // combine the two half-warp edge-streams
#pragma unroll
    for (int k = 0; k < 8; k++) acc[k] += __shfl_xor_sync(0xffffffffu, acc[k], 16);

    float inv = (den > 0.f) ? (1.f / den) : 0.f;
    if (grp == 0) {
        float4 o0 = make_float4(acc[0] * inv, acc[1] * inv, acc[2] * inv, acc[3] * inv);
        float4 o1 = make_float4(acc[4] * inv, acc[5] * inv, acc[6] * inv, acc[7] * inv);
        float4* op = (float4*)(out + (size_t)gw * DIM + sub * 8);
        op[0] = o0;
        op[1] = o1;
    }
}

// ---------------- launch --------------------------------------------------------
extern "C" void kernel_launch(void* const* d_in, const int* in_sizes, int n_in,
                              void* d_out, int out_size) {
    const float* feat   = (const float*)d_in[0];
    const int*   src    = (const int*)d_in[1];
    const int*   dst    = (const int*)d_in[2];
    const float* W      = (const float*)d_in[3];
    const float* bias   = (const float*)d_in[4];
    const float* attn_w = (const float*)d_in[5];
    const float* attn_b = (const float*)d_in[6];
    const float* mask   = (const float*)d_in[7];
    float* out = (float*)d_out;

    int N = in_sizes[0] / DIM;   // 50000
    int E = in_sizes[1];         // 1600000

    static cudaStream_t s_side = nullptr;
    static cudaEvent_t ev_fork = nullptr, ev_join = nullptr;
    if (s_side == nullptr) {
        cudaStreamCreateWithFlags(&s_side, cudaStreamNonBlocking);
        cudaEventCreateWithFlags(&ev_fork, cudaEventDisableTiming);
        cudaEventCreateWithFlags(&ev_join, cudaEventDisableTiming);
    }

    // fork: CSR-build chain (depends only on dst) runs beside prep+GEMM
    cudaEventRecord(ev_fork, 0);
    cudaStreamWaitEvent(s_side, ev_fork, 0);

    int e4 = (E + 3) / 4;
    int nb = (N + SCAN_CH - 1) / SCAN_CH;   // 25
    zero_deg_kernel<<<(N + 255) / 256, 256, 0, s_side>>>(N);
    hist_kernel<<<(e4 + 255) / 256, 256, 0, s_side>>>(dst, E);
    scan1_kernel<<<nb, 512, 0, s_side>>>(N);
    scan2_kernel<<<1, 32, 0, s_side>>>(nb, N);
    scan3_kernel<<<(N + 255) / 256, 256, 0, s_side>>>(N);
    cudaEventRecord(ev_join, s_side);

    // main stream: W fold + GEMM (+ fused scores, fp16 h)
    prep_w_kernel<<<(DIM * DIM + 255) / 256, 256>>>(W, mask);
    size_t smem = (size_t)(128 * 64 + 128 * 128) * sizeof(float);  // 96KB
    cudaFuncSetAttribute(gemm_kernel, cudaFuncAttributeMaxDynamicSharedMemorySize, (int)smem);
    gemm_kernel<<<(N + GB_M - 1) / GB_M, 128, smem>>>(feat, bias, attn_w, N);

    // join, then scatter + aggregate
    cudaStreamWaitEvent(0, ev_join, 0);
    scatter_kernel<<<(e4 + 255) / 256, 256>>>(src, dst, E);
    agg_kernel<<<(N * 32 + 255) / 256, 256>>>(out, attn_b, N);
}